// round 17
// baseline (speedup 1.0000x reference)
#include <cuda_runtime.h>
#include <cstdint>
#include <math.h>

typedef unsigned long long ull;
struct __align__(16) ULL2 { ull x, y; };

__device__ float g_h1[32*64*64*64];
__device__ float g_h2[32*64*64*64];
__device__ float g_logits64[32*64*64];
__device__ float g_w1r[256*9*64];
__device__ float g_w2r[64*9*64];
#define PQ 8
__device__ float g_ppv[32*PQ*4]; __device__ int g_ppi[32*PQ*4];
__device__ float g_npv[32*PQ*5]; __device__ int g_npi[32*PQ*5];

__device__ __forceinline__ ull pk2(float lo, float hi)
{ ull r; asm("mov.b64 %0, {%1, %2};" : "=l"(r) : "f"(lo), "f"(hi)); return r; }
__device__ __forceinline__ void upk2(ull v, float& lo, float& hi)
{ asm("mov.b64 {%0, %1}, %2;" : "=f"(lo), "=f"(hi) : "l"(v)); }
__device__ __forceinline__ void fma2(ull& d, ull a, ull b)
{ asm("fma.rn.f32x2 %0, %1, %2, %0;" : "+l"(d) : "l"(a), "l"(b)); }

__device__ __forceinline__ void cp4_zfill(uint32_t d, const void* s, int sz)
{ asm volatile("cp.async.ca.shared.global [%0], [%1], 4, %2;" :: "r"(d), "l"(s), "r"(sz)); }
__device__ __forceinline__ void cp16(uint32_t d, const void* s)
{ asm volatile("cp.async.cg.shared.global [%0], [%1], 16;" :: "r"(d), "l"(s)); }
__device__ __forceinline__ void cp_commit() { asm volatile("cp.async.commit_group;"); }
template<int N> __device__ __forceinline__ void cp_wait()
{ asm volatile("cp.async.wait_group %0;" :: "n"(N) : "memory"); }

__global__ void k_reformat(const float* __restrict__ W, float* __restrict__ out, int cin)
{
    int i = blockIdx.x * blockDim.x + threadIdx.x;
    if (i >= 64 * cin * 9) return;
    int oc = i & 63, rest = i >> 6, tap = rest % 9, ic = rest / 9;
    out[i] = W[(oc * cin + ic) * 9 + tap];
}

// ---- 3x3 conv + BN + ReLU (byte-identical to 949.6us winner) ----
#define BUF_F 7200
template<int CIN>
__global__ __launch_bounds__(256, 2)
void k_conv3x3(const float* __restrict__ in, float* __restrict__ out,
               const float* __restrict__ wr,
               const float* __restrict__ gg, const float* __restrict__ bb,
               const float* __restrict__ mm, const float* __restrict__ vv)
{
    extern __shared__ float dsm[];

    const int b    = blockIdx.y;
    const int tile = blockIdx.x;
    const int ty0  = (tile >> 2) * 16;
    const int tx0  = (tile & 3) * 16;
    const int tid  = threadIdx.x;
    const int t_oc = tid >> 5;
    const int t_px = tid & 31;
    const int row  = t_px >> 1;
    const int seg  = (t_px & 1) * 8;

    const uint32_t sb = (uint32_t)__cvta_generic_to_shared(dsm);

    auto stage = [&](int c0, int d) {
        uint32_t in_dst = sb + d * (BUF_F * 4);
        uint32_t w_dst  = in_dst + 2592 * 4;
        #pragma unroll
        for (int k = 0; k < 11; ++k) {
            int i = tid + k * 256;
            if (i < 2592) {
                int icl = i / 324;
                int rem = i - icl * 324;
                int yy  = rem / 18;
                int xx  = rem - yy * 18;
                int gy = ty0 - 1 + yy, gx = tx0 - 1 + xx;
                bool ok = ((unsigned)gy < 64u) & ((unsigned)gx < 64u);
                const float* src = ok ? &in[((b * CIN + c0 + icl) * 64 + gy) * 64 + gx] : in;
                cp4_zfill(in_dst + i * 4, src, ok ? 4 : 0);
            }
        }
        #pragma unroll
        for (int k = 0; k < 5; ++k) {
            int i = tid + k * 256;
            if (i < 1152) cp16(w_dst + i * 16, &wr[c0 * 576 + i * 4]);
        }
        cp_commit();
    };

    ull acc[8][4];
    #pragma unroll
    for (int j = 0; j < 8; ++j)
        #pragma unroll
        for (int k = 0; k < 4; ++k) acc[j][k] = 0ull;

    const int nchunk = CIN / 8;
    stage(0, 0);
    if (nchunk > 1) stage(8, 1);

    int dc = 0;
    for (int c = 0; c < nchunk; ++c) {
        if (c + 1 < nchunk) cp_wait<1>(); else cp_wait<0>();
        __syncthreads();
        if (c + 2 < nchunk) {
            int ds = dc + 2; if (ds >= 3) ds -= 3;
            stage((c + 2) * 8, ds);
        }

        const float* s_in = dsm + dc * BUF_F;
        const float* s_w  = s_in + 2592;
        #pragma unroll 4
        for (int icl = 0; icl < 8; ++icl) {
            const float* si = &s_in[icl * 324 + row * 18 + seg];
            const float* sw = &s_w[icl * 576 + t_oc * 8];
            #pragma unroll
            for (int ty = 0; ty < 3; ++ty) {
                ull rin2[10];
                #pragma unroll
                for (int xx = 0; xx < 10; ++xx) {
                    float v = si[ty * 18 + xx];
                    rin2[xx] = pk2(v, v);
                }
                #pragma unroll
                for (int tx = 0; tx < 3; ++tx) {
                    const int tap = ty * 3 + tx;
                    const ULL2 wA = *(const ULL2*)&sw[tap * 64];
                    const ULL2 wB = *(const ULL2*)&sw[tap * 64 + 4];
                    #pragma unroll
                    for (int j = 0; j < 8; ++j) {
                        ull xp = rin2[j + tx];
                        fma2(acc[j][0], xp, wA.x);
                        fma2(acc[j][1], xp, wA.y);
                        fma2(acc[j][2], xp, wB.x);
                        fma2(acc[j][3], xp, wB.y);
                    }
                }
            }
        }
        if (++dc == 3) dc = 0;
    }

    const int y = ty0 + row, x = tx0 + seg;
    #pragma unroll
    for (int kp = 0; kp < 4; ++kp) {
        int oc0 = t_oc * 8 + 2 * kp, oc1 = oc0 + 1;
        float sc0 = gg[oc0] / sqrtf(vv[oc0] + 1e-5f);
        float sh0 = bb[oc0] - mm[oc0] * sc0;
        float sc1 = gg[oc1] / sqrtf(vv[oc1] + 1e-5f);
        float sh1 = bb[oc1] - mm[oc1] * sc1;
        float a0[8], a1[8];
        #pragma unroll
        for (int j = 0; j < 8; ++j) upk2(acc[j][kp], a0[j], a1[j]);

        float4 o0, o1;
        o0.x = fmaxf(fmaf(a0[0], sc0, sh0), 0.f);
        o0.y = fmaxf(fmaf(a0[1], sc0, sh0), 0.f);
        o0.z = fmaxf(fmaf(a0[2], sc0, sh0), 0.f);
        o0.w = fmaxf(fmaf(a0[3], sc0, sh0), 0.f);
        o1.x = fmaxf(fmaf(a0[4], sc0, sh0), 0.f);
        o1.y = fmaxf(fmaf(a0[5], sc0, sh0), 0.f);
        o1.z = fmaxf(fmaf(a0[6], sc0, sh0), 0.f);
        o1.w = fmaxf(fmaf(a0[7], sc0, sh0), 0.f);
        float* dst0 = &out[((b * 64 + oc0) * 64 + y) * 64 + x];
        *(float4*)dst0 = o0;
        *(float4*)(dst0 + 4) = o1;

        o0.x = fmaxf(fmaf(a1[0], sc1, sh1), 0.f);
        o0.y = fmaxf(fmaf(a1[1], sc1, sh1), 0.f);
        o0.z = fmaxf(fmaf(a1[2], sc1, sh1), 0.f);
        o0.w = fmaxf(fmaf(a1[3], sc1, sh1), 0.f);
        o1.x = fmaxf(fmaf(a1[4], sc1, sh1), 0.f);
        o1.y = fmaxf(fmaf(a1[5], sc1, sh1), 0.f);
        o1.z = fmaxf(fmaf(a1[6], sc1, sh1), 0.f);
        o1.w = fmaxf(fmaf(a1[7], sc1, sh1), 0.f);
        float* dst1 = &out[((b * 64 + oc1) * 64 + y) * 64 + x];
        *(float4*)dst1 = o0;
        *(float4*)(dst1 + 4) = o1;
    }
}

__global__ void k_conv1x1(const float* __restrict__ in, const float* __restrict__ w3,
                          const float* __restrict__ b3, float* __restrict__ out)
{
    int i = blockIdx.x * blockDim.x + threadIdx.x;
    int b = i >> 12, p = i & 4095;
    const float* base = in + (size_t)(b * 64) * 4096 + p;
    float s = 0.f;
    #pragma unroll 8
    for (int ic = 0; ic < 64; ++ic)
        s = fmaf(base[(size_t)ic * 4096], __ldg(&w3[ic]), s);
    out[i] = s + b3[0];
}

__global__ void k_resize(const float* __restrict__ lg,
                         float* __restrict__ heat, float* __restrict__ logits_out)
{
    int ox = threadIdx.x, oy = blockIdx.x, b = blockIdx.y;
    float sy = 0.25f * oy - 0.375f;
    float sx = 0.25f * ox - 0.375f;
    int y0; float fy;
    if (sy <= 0.f)       { y0 = 0;  fy = 0.f; }
    else if (sy >= 63.f) { y0 = 62; fy = 1.f; }
    else                 { y0 = (int)sy; fy = sy - (float)y0; }
    int x0; float fx;
    if (sx <= 0.f)       { x0 = 0;  fx = 0.f; }
    else if (sx >= 63.f) { x0 = 62; fx = 1.f; }
    else                 { x0 = (int)sx; fx = sx - (float)x0; }
    const float* src = lg + b * 4096;
    float v00 = src[y0 * 64 + x0],     v01 = src[y0 * 64 + x0 + 1];
    float v10 = src[(y0+1) * 64 + x0], v11 = src[(y0+1) * 64 + x0 + 1];
    float a = v00 * (1.f - fx) + v01 * fx;
    float c = v10 * (1.f - fx) + v11 * fx;
    float val = a * (1.f - fy) + c * fy;
    int o = b * 65536 + oy * 256 + ox;
    logits_out[o] = val;
    heat[o] = 1.f / (1.f + expf(-val));
}

__device__ __forceinline__ void ins3(float h, int p, float* bv, int* bi)
{
    if (h > bv[0] || (h == bv[0] && p < bi[0])) {
        bv[2]=bv[1]; bi[2]=bi[1]; bv[1]=bv[0]; bi[1]=bi[0]; bv[0]=h; bi[0]=p;
    } else if (h > bv[1] || (h == bv[1] && p < bi[1])) {
        bv[2]=bv[1]; bi[2]=bi[1]; bv[1]=h; bi[1]=p;
    } else if (h > bv[2] || (h == bv[2] && p < bi[2])) {
        bv[2]=h; bi[2]=p;
    }
}
__device__ __forceinline__ void ins5tb(float h, int p, float* bv, int* bi)
{
    #pragma unroll
    for (int k = 0; k < 5; ++k) {
        if (h > bv[k] || (h == bv[k] && p < bi[k])) {
            #pragma unroll
            for (int m = 4; m > k; --m) { bv[m] = bv[m-1]; bi[m] = bi[m-1]; }
            bv[k] = h; bi[k] = p;
            break;
        }
    }
}

__device__ __forceinline__ void threefry2x32_dev(unsigned c0, unsigned c1,
                                                 unsigned &o0, unsigned &o1)
{
    const unsigned ks0 = 0u, ks1 = 42u, ks2 = 0x1BD11BDAu ^ 0u ^ 42u;
    unsigned x0 = c0 + ks0, x1 = c1 + ks1;
#define TFR(d) { x0 += x1; x1 = (x1 << d) | (x1 >> (32 - d)); x1 ^= x0; }
    TFR(13) TFR(15) TFR(26) TFR(6)  x0 += ks1; x1 += ks2 + 1u;
    TFR(17) TFR(29) TFR(16) TFR(24) x0 += ks2; x1 += ks0 + 2u;
    TFR(13) TFR(15) TFR(26) TFR(6)  x0 += ks0; x1 += ks1 + 3u;
    TFR(17) TFR(29) TFR(16) TFR(24) x0 += ks1; x1 += ks2 + 4u;
    TFR(13) TFR(15) TFR(26) TFR(6)  x0 += ks2; x1 += ks0 + 5u;
#undef TFR
    o0 = x0; o1 = x1;
}

// ---- fused point kernel: vmax + peak top-3 + argmax + neg top-5 in one pass
// Block (q,b): rows [q*32, q*32+32). smem: 40 heat rows (-inf padded) + 32 vm
// rows. Negatives are top-5 WITHOUT pos-exclusion (at most 3 positions are
// ever excluded, so global top-5 filtered at merge == reference top-2).
__global__ void k_points(const float* __restrict__ heat)
{
    extern __shared__ float sm[];
    float* shh = sm;            // 40*256 = 10240 floats
    float* shv = sm + 10240;    // 32*256 =  8192 floats

    const int b = blockIdx.y, q = blockIdx.x, tid = threadIdx.x;
    const float* hb = heat + b * 65536;
    const int r0 = q * 32;

    for (int i = tid; i < 10240; i += 256) {
        int yy = (i >> 8) + r0 - 4, x = i & 255;
        shh[i] = ((unsigned)yy < 256u) ? hb[yy * 256 + x] : -INFINITY;
    }
    __syncthreads();
    for (int i = tid; i < 8192; i += 256) {
        int yl = i >> 8, x = i & 255;
        float mv = -INFINITY;
        #pragma unroll
        for (int dy = 0; dy < 9; ++dy) mv = fmaxf(mv, shh[(yl + dy) * 256 + x]);
        shv[i] = mv;
    }
    __syncthreads();

    float tv[3] = {-INFINITY,-INFINITY,-INFINITY};
    int   ti[3] = {0x7fffffff,0x7fffffff,0x7fffffff};
    float av = -INFINITY; int ai = 0x7fffffff;
    float nv[5] = {-INFINITY,-INFINITY,-INFINITY,-INFINITY,-INFINITY};
    int   ni[5] = {0x7fffffff,0x7fffffff,0x7fffffff,0x7fffffff,0x7fffffff};

    for (int i = tid; i < 8192; i += 256) {     // ascending p per thread
        int yl = i >> 8, x = i & 255;
        int p = (r0 + yl) * 256 + x;
        float h = shh[(yl + 4) * 256 + x];
        if (h > av) { av = h; ai = p; }
        float mx = -INFINITY;
        #pragma unroll
        for (int dx = -4; dx <= 4; ++dx) {
            int xx = x + dx;
            if ((unsigned)xx < 256u) mx = fmaxf(mx, shv[yl * 256 + xx]);
        }
        if (h == mx && h > 0.1f) {
            if (h > tv[0]) {
                tv[2]=tv[1]; ti[2]=ti[1]; tv[1]=tv[0]; ti[1]=ti[0]; tv[0]=h; ti[0]=p;
            } else if (h > tv[1]) {
                tv[2]=tv[1]; ti[2]=ti[1]; tv[1]=h; ti[1]=p;
            } else if (h > tv[2]) {
                tv[2]=h; ti[2]=p;
            }
        }
        if (h < 0.3f) {
            unsigned w0, w1;
            threefry2x32_dev(0u, (unsigned)(b * 65536 + p), w0, w1);
            float r = __uint_as_float(((w0 ^ w1) >> 9) | 0x3f800000u) - 1.0f;
            #pragma unroll
            for (int k = 0; k < 5; ++k) {       // plain >: ascending keeps earliest
                if (r > nv[k]) {
                    #pragma unroll
                    for (int m = 4; m > k; --m) { nv[m] = nv[m-1]; ni[m] = ni[m-1]; }
                    nv[k] = r; ni[k] = p;
                    break;
                }
            }
        }
    }
    __syncthreads();   // shh/shv no longer needed; reuse sm for reduction

    // per-thread 9 slots: [0..2] peaks, [3] argmax, [4..8] negs
    float* rv = sm;                      // 256*9 floats
    int*   ri = (int*)(sm + 2304);       // 256*9 ints
    #pragma unroll
    for (int k = 0; k < 3; ++k) { rv[tid*9+k] = tv[k]; ri[tid*9+k] = ti[k]; }
    rv[tid*9+3] = av; ri[tid*9+3] = ai;
    #pragma unroll
    for (int k = 0; k < 5; ++k) { rv[tid*9+4+k] = nv[k]; ri[tid*9+4+k] = ni[k]; }
    __shared__ float wvv[8*9];
    __shared__ int   wii[8*9];
    __syncthreads();

    if ((tid & 31) == 0) {
        int w = tid >> 5;
        float bv[3] = {-INFINITY,-INFINITY,-INFINITY};
        int   bi[3] = {0x7fffffff,0x7fffffff,0x7fffffff};
        float bav = -INFINITY; int bai = 0x7fffffff;
        float bn[5] = {-INFINITY,-INFINITY,-INFINITY,-INFINITY,-INFINITY};
        int   bj[5] = {0x7fffffff,0x7fffffff,0x7fffffff,0x7fffffff,0x7fffffff};
        for (int t = tid; t < tid + 32; ++t) {
            #pragma unroll
            for (int k = 0; k < 3; ++k) {
                float h = rv[t*9+k];
                if (h != -INFINITY) ins3(h, ri[t*9+k], bv, bi);
            }
            float a2 = rv[t*9+3]; int i2 = ri[t*9+3];
            if (a2 > bav || (a2 == bav && i2 < bai)) { bav = a2; bai = i2; }
            #pragma unroll
            for (int k = 0; k < 5; ++k) {
                float r = rv[t*9+4+k];
                if (r != -INFINITY) ins5tb(r, ri[t*9+4+k], bn, bj);
            }
        }
        #pragma unroll
        for (int k = 0; k < 3; ++k) { wvv[w*9+k] = bv[k]; wii[w*9+k] = bi[k]; }
        wvv[w*9+3] = bav; wii[w*9+3] = bai;
        #pragma unroll
        for (int k = 0; k < 5; ++k) { wvv[w*9+4+k] = bn[k]; wii[w*9+4+k] = bj[k]; }
    }
    __syncthreads();

    if (tid == 0) {
        float bv[3] = {-INFINITY,-INFINITY,-INFINITY};
        int   bi[3] = {0x7fffffff,0x7fffffff,0x7fffffff};
        float bav = -INFINITY; int bai = 0x7fffffff;
        float bn[5] = {-INFINITY,-INFINITY,-INFINITY,-INFINITY,-INFINITY};
        int   bj[5] = {0x7fffffff,0x7fffffff,0x7fffffff,0x7fffffff,0x7fffffff};
        for (int w = 0; w < 8; ++w) {
            #pragma unroll
            for (int k = 0; k < 3; ++k) {
                float h = wvv[w*9+k];
                if (h != -INFINITY) ins3(h, wii[w*9+k], bv, bi);
            }
            float a2 = wvv[w*9+3]; int i2 = wii[w*9+3];
            if (a2 > bav || (a2 == bav && i2 < bai)) { bav = a2; bai = i2; }
            #pragma unroll
            for (int k = 0; k < 5; ++k) {
                float r = wvv[w*9+4+k];
                if (r != -INFINITY) ins5tb(r, wii[w*9+4+k], bn, bj);
            }
        }
        int o = (b * PQ + q) * 4;
        #pragma unroll
        for (int k = 0; k < 3; ++k) { g_ppv[o+k] = bv[k]; g_ppi[o+k] = bi[k]; }
        g_ppv[o+3] = bav; g_ppi[o+3] = bai;
        int on = (b * PQ + q) * 5;
        #pragma unroll
        for (int k = 0; k < 5; ++k) { g_npv[on+k] = bn[k]; g_npi[on+k] = bj[k]; }
    }
}

// ---- final merge: pos top-3 + argmax fallback; neg = global top-5 filtered
// against valid pos (exact reference penalized-top-2 ordering); assemble.
__global__ void k_final(float* __restrict__ coords, float* __restrict__ labels)
{
    int b = threadIdx.x;
    if (b >= 32) return;

    float bv[3] = {-INFINITY,-INFINITY,-INFINITY};
    int   bi[3] = {0x7fffffff,0x7fffffff,0x7fffffff};
    float bav = -INFINITY; int bai = 0x7fffffff;
    for (int q = 0; q < PQ; ++q) {
        int o = (b * PQ + q) * 4;
        #pragma unroll
        for (int k = 0; k < 3; ++k) {
            float h = g_ppv[o+k];
            if (h != -INFINITY) ins3(h, g_ppi[o+k], bv, bi);
        }
        float avv = g_ppv[o+3]; int aii = g_ppi[o+3];
        if (avv > bav || (avv == bav && aii < bai)) { bav = avv; bai = aii; }
    }
    int pos_idx[3], pos_valid[3];
    pos_idx[0]   = (bv[0] != -INFINITY) ? bi[0] : bai;
    pos_valid[0] = 1;
    pos_idx[1]   = bi[1]; pos_valid[1] = (bv[1] != -INFINITY) ? 1 : 0;
    pos_idx[2]   = bi[2]; pos_valid[2] = (bv[2] != -INFINITY) ? 1 : 0;

    float bn[5] = {-INFINITY,-INFINITY,-INFINITY,-INFINITY,-INFINITY};
    int   bj[5] = {0x7fffffff,0x7fffffff,0x7fffffff,0x7fffffff,0x7fffffff};
    for (int q = 0; q < PQ; ++q) {
        int on = (b * PQ + q) * 5;
        #pragma unroll
        for (int k = 0; k < 5; ++k) {
            float r = g_npv[on+k];
            if (r != -INFINITY) ins5tb(r, g_npi[on+k], bn, bj);
        }
    }
    int neg_idx[2] = {0, 0}, neg_valid[2] = {0, 0};
    int taken = 0;
    for (int k = 0; k < 5 && taken < 2; ++k) {
        if (bn[k] == -INFINITY) break;
        int p = bj[k];
        bool excl = (pos_valid[0] && p == pos_idx[0]) ||
                    (pos_valid[1] && p == pos_idx[1]) ||
                    (pos_valid[2] && p == pos_idx[2]);
        if (!excl) { neg_idx[taken] = p; neg_valid[taken] = 1; ++taken; }
    }

    int idxs[5], valid[5]; float lab[5];
    #pragma unroll
    for (int k = 0; k < 3; ++k) { idxs[k] = pos_idx[k]; valid[k] = pos_valid[k]; lab[k] = 1.f; }
    idxs[3] = neg_idx[0]; valid[3] = neg_valid[0]; lab[3] = 0.f;
    idxs[4] = neg_idx[1]; valid[4] = neg_valid[1]; lab[4] = 0.f;

    float cx[5], cy[5], cl[5];
    #pragma unroll
    for (int s = 0; s < 5; ++s) { cx[s] = 0.f; cy[s] = 0.f; cl[s] = -1.f; }
    int cnt = 0;
    for (int k = 0; k < 5; ++k) {
        if (valid[k]) {
            cx[cnt] = (float)(idxs[k] & 255);
            cy[cnt] = (float)(idxs[k] >> 8);
            cl[cnt] = lab[k];
            ++cnt;
        }
    }
    for (int s = 0; s < 5; ++s) {
        coords[b*10 + s*2 + 0] = cx[s];
        coords[b*10 + s*2 + 1] = cy[s];
        labels[b*5 + s] = cl[s];
    }
}

extern "C" void kernel_launch(void* const* d_in, const int* in_sizes, int n_in,
                              void* d_out, int out_size)
{
    const float* x  = (const float*)d_in[0];
    const float* W1 = (const float*)d_in[1];
    const float* g1 = (const float*)d_in[2];
    const float* b1 = (const float*)d_in[3];
    const float* m1 = (const float*)d_in[4];
    const float* v1 = (const float*)d_in[5];
    const float* W2 = (const float*)d_in[6];
    const float* g2 = (const float*)d_in[7];
    const float* b2 = (const float*)d_in[8];
    const float* m2 = (const float*)d_in[9];
    const float* v2 = (const float*)d_in[10];
    const float* W3 = (const float*)d_in[11];
    const float* b3 = (const float*)d_in[12];

    float* out    = (float*)d_out;
    float* heat   = out;
    float* coords = out + 2097152;
    float* labels = out + 2097472;
    float* logits = out + 2097632;

    float *p_h1, *p_h2, *p_l64, *p_w1r, *p_w2r;
    cudaGetSymbolAddress((void**)&p_h1,  g_h1);
    cudaGetSymbolAddress((void**)&p_h2,  g_h2);
    cudaGetSymbolAddress((void**)&p_l64, g_logits64);
    cudaGetSymbolAddress((void**)&p_w1r, g_w1r);
    cudaGetSymbolAddress((void**)&p_w2r, g_w2r);

    const int SMEMSZ = 3 * BUF_F * 4;        // 86400 B
    const int PSMEM  = (10240 + 8192) * 4;   // 73728 B
    static bool attr_done = false;
    if (!attr_done) {
        cudaFuncSetAttribute(k_conv3x3<256>, cudaFuncAttributeMaxDynamicSharedMemorySize, SMEMSZ);
        cudaFuncSetAttribute(k_conv3x3<64>,  cudaFuncAttributeMaxDynamicSharedMemorySize, SMEMSZ);
        cudaFuncSetAttribute(k_points,       cudaFuncAttributeMaxDynamicSharedMemorySize, PSMEM);
        attr_done = true;
    }

    k_reformat<<<576, 256>>>(W1, p_w1r, 256);
    k_reformat<<<144, 256>>>(W2, p_w2r, 64);

    k_conv3x3<256><<<dim3(16, 32), 256, SMEMSZ>>>(x,    p_h1, p_w1r, g1, b1, m1, v1);
    k_conv3x3<64> <<<dim3(16, 32), 256, SMEMSZ>>>(p_h1, p_h2, p_w2r, g2, b2, m2, v2);

    k_conv1x1<<<512, 256>>>(p_h2, W3, b3, p_l64);
    k_resize<<<dim3(256, 32), 256>>>(p_l64, heat, logits);

    k_points<<<dim3(PQ, 32), 256, PSMEM>>>(heat);
    k_final<<<1, 32>>>(coords, labels);
}